// round 16
// baseline (speedup 1.0000x reference)
#include <cuda_runtime.h>
#include <cstdint>

#define BB   16
#define CC   3
#define HH   512
#define WW   512
#define CUT  224
#define CUTN 32

#define BAND    16
#define NBANDS  (HH / BAND)     // 32
#define THREADS 256
#define NWARPS  (THREADS / 32)  // 8

// Block = (16-input-row band, plane bc). All (cut, output-row) tasks sourced
// from this band are processed here; the 32KB band stays L1-resident so
// cross-cut re-reads of x hit L1. Warps take CONTIGUOUS task chunks so the
// per-cut gather-column indices are computed once per cut, not once per row.
__global__ __launch_bounds__(THREADS) void make_cutouts_kernel(
    const float* __restrict__ x,
    const int*   __restrict__ sizes,
    const int*   __restrict__ offx,
    const int*   __restrict__ offy,
    float*       __restrict__ out)
{
    const int band = blockIdx.x;          // [0, 32)
    const int bc   = blockIdx.y;          // [0, 48)
    const int y0   = band * BAND;

    __shared__ int s_sz[CUTN], s_ox[CUTN], s_oy[CUTN], s_ilo[CUTN];
    __shared__ int s_pfx[CUTN + 1];

    const int tid = threadIdx.x;

    // Per-cut: output rows i with yidx(i) = oy + i*sz/224 in [y0, y0+BAND)
    if (tid < CUTN) {
        const int sz = sizes[tid];
        s_sz[tid] = sz; s_ox[tid] = offx[tid];
        const int oy = offy[tid];
        s_oy[tid] = oy;

        const int a  = y0 - oy;
        const int A  = a > 0 ? a : 0;
        const int Bb = a + BAND;

        int ilo = (CUT * A + sz - 1) / sz;
        if (ilo > CUT) ilo = CUT;
        int ihi = 0;
        if (Bb > 0) {
            ihi = (CUT * Bb + sz - 1) / sz;
            if (ihi > CUT) ihi = CUT;
        }
        int cnt = ihi - ilo;
        if (cnt < 0) cnt = 0;
        s_ilo[tid]     = ilo;
        s_pfx[tid + 1] = cnt;
    }
    __syncthreads();
    if (tid == 0) {
        int acc = 0;
        s_pfx[0] = 0;
        #pragma unroll
        for (int k = 0; k < CUTN; ++k) { acc += s_pfx[k + 1]; s_pfx[k + 1] = acc; }
    }
    __syncthreads();

    const int total = s_pfx[CUTN];
    const int wid   = tid >> 5;
    const int lane  = tid & 31;

    // Contiguous chunk per warp (cut-major -> few cut switches per warp)
    const int chunk = (total + NWARPS - 1) / NWARPS;
    int       t     = wid * chunk;
    const int tend  = (t + chunk < total) ? (t + chunk) : total;

    const float* __restrict__ xplane = x + (size_t)bc * (HH * WW);

    int cur = 0;
    while (t < tend) {
        while (t >= s_pfx[cur + 1]) ++cur;
        const int n   = cur;
        const int sz  = s_sz[n];
        const int ox  = s_ox[n];
        const int oy  = s_oy[n];
        const int hi  = (tend < s_pfx[n + 1]) ? tend : s_pfx[n + 1];
        int       i   = s_ilo[n] + (t - s_pfx[n]);
        const int cnt = hi - t;

        // Gather-column indices: once per cut (amortized over cnt rows)
        int xi0 = ox + ((0 * 32 + lane) * sz) / CUT;
        int xi1 = ox + ((1 * 32 + lane) * sz) / CUT;
        int xi2 = ox + ((2 * 32 + lane) * sz) / CUT;
        int xi3 = ox + ((3 * 32 + lane) * sz) / CUT;
        int xi4 = ox + ((4 * 32 + lane) * sz) / CUT;
        int xi5 = ox + ((5 * 32 + lane) * sz) / CUT;
        int xi6 = ox + ((6 * 32 + lane) * sz) / CUT;

        float* __restrict__ obase =
            out + ((size_t)(n * (BB * CC) + bc)) * (CUT * CUT);

        int q = i * sz;   // running numerator for y = oy + q/224
        #pragma unroll 2
        for (int r = 0; r < cnt; ++r) {
            const int y = oy + q / CUT;
            q += sz;
            const float* __restrict__ row = xplane + (size_t)y * WW;

            float v0 = row[xi0], v1 = row[xi1], v2 = row[xi2], v3 = row[xi3];
            float v4 = row[xi4], v5 = row[xi5], v6 = row[xi6];

            float* __restrict__ orow = obase + (size_t)(i + r) * CUT + lane;
            __stcs(orow +   0, v0);
            __stcs(orow +  32, v1);
            __stcs(orow +  64, v2);
            __stcs(orow +  96, v3);
            __stcs(orow + 128, v4);
            __stcs(orow + 160, v5);
            __stcs(orow + 192, v6);
        }
        t = hi;
    }
}

extern "C" void kernel_launch(void* const* d_in, const int* in_sizes, int n_in,
                              void* d_out, int out_size)
{
    const float* x     = (const float*)d_in[0];
    const int*   sizes = (const int*)d_in[1];
    const int*   ox    = (const int*)d_in[2];
    const int*   oy    = (const int*)d_in[3];
    float*       out   = (float*)d_out;

    dim3 grid(NBANDS, BB * CC);
    dim3 block(THREADS);
    make_cutouts_kernel<<<grid, block>>>(x, sizes, ox, oy, out);
}

// round 17
// speedup vs baseline: 1.2908x; 1.2908x over previous
#include <cuda_runtime.h>
#include <cstdint>

#define BB   16
#define CC   3
#define HH   512
#define WW   512
#define CUT  224
#define CUTN 32

#define BAND    4
#define NBANDS  (HH / BAND)       // 128
#define NPAIRS  ((BB * CC) / 2)   // 24 plane-pairs
#define THREADS 256
#define NWARPS  (THREADS / 32)    // 8

// Block = (4-input-row band, plane PAIR). Tasks = (cut, output-row) sourced
// from this band, distributed round-robin across warps (balanced, like R13).
// Each task computes gather indices ONCE and applies them to BOTH planes:
// index ALU per element halves vs R13 while grid shape / L1 footprint /
// balance stay identical to the 64.3us kernel.
__global__ __launch_bounds__(THREADS) void make_cutouts_kernel(
    const float* __restrict__ x,
    const int*   __restrict__ sizes,
    const int*   __restrict__ offx,
    const int*   __restrict__ offy,
    float*       __restrict__ out)
{
    const int band = blockIdx.x;          // [0, 128)
    const int bcp  = blockIdx.y;          // [0, 24) -> planes 2*bcp, 2*bcp+1
    const int y0   = band * BAND;

    __shared__ int s_sz[CUTN], s_ox[CUTN], s_oy[CUTN], s_ilo[CUTN];
    __shared__ int s_pfx[CUTN + 1];

    const int tid = threadIdx.x;

    // Per-cut: output rows i with yidx(i) = oy + i*sz/224 in [y0, y0+BAND)
    if (tid < CUTN) {
        const int sz = sizes[tid];
        const int ox = offx[tid];
        const int oy = offy[tid];
        s_sz[tid] = sz; s_ox[tid] = ox; s_oy[tid] = oy;

        const int a  = y0 - oy;
        const int A  = a > 0 ? a : 0;
        const int Bb = a + BAND;

        int ilo = (CUT * A + sz - 1) / sz;
        if (ilo > CUT) ilo = CUT;
        int ihi = 0;
        if (Bb > 0) {
            ihi = (CUT * Bb + sz - 1) / sz;
            if (ihi > CUT) ihi = CUT;
        }
        int cnt = ihi - ilo;
        if (cnt < 0) cnt = 0;
        s_ilo[tid]     = ilo;
        s_pfx[tid + 1] = cnt;
    }
    __syncthreads();
    if (tid == 0) {
        int acc = 0;
        s_pfx[0] = 0;
        #pragma unroll
        for (int k = 0; k < CUTN; ++k) { acc += s_pfx[k + 1]; s_pfx[k + 1] = acc; }
    }
    __syncthreads();

    const int total = s_pfx[CUTN];
    const int wid   = tid >> 5;
    const int lane  = tid & 31;

    const int bc0 = bcp * 2;
    const float* __restrict__ xplane0 = x + (size_t)bc0 * (HH * WW);
    const float* __restrict__ xplane1 = xplane0 + (HH * WW);

    // Round-robin tasks (balanced); forward scan for cut lookup.
    int cur = 0;
    for (int t = wid; t < total; t += NWARPS) {
        while (t >= s_pfx[cur + 1]) ++cur;
        const int n  = cur;
        const int sz = s_sz[n];
        const int ox = s_ox[n];
        const int oy = s_oy[n];
        const int i  = s_ilo[n] + (t - s_pfx[n]);
        const int y  = oy + (i * sz) / CUT;

        // Gather-column indices: computed once, used for both planes
        const int xi0 = ox + ((0 * 32 + lane) * sz) / CUT;
        const int xi1 = ox + ((1 * 32 + lane) * sz) / CUT;
        const int xi2 = ox + ((2 * 32 + lane) * sz) / CUT;
        const int xi3 = ox + ((3 * 32 + lane) * sz) / CUT;
        const int xi4 = ox + ((4 * 32 + lane) * sz) / CUT;
        const int xi5 = ox + ((5 * 32 + lane) * sz) / CUT;
        const int xi6 = ox + ((6 * 32 + lane) * sz) / CUT;

        const size_t rowoff = (size_t)y * WW;
        const size_t ooff   = (size_t)i * CUT + lane;
        float* __restrict__ orow0 =
            out + ((size_t)(n * (BB * CC) + bc0)) * (CUT * CUT) + ooff;
        float* __restrict__ orow1 = orow0 + (size_t)(CUT * CUT);

        // Plane 0: batch 7 L1-hot gathers, then 7 coalesced streaming stores
        {
            const float* __restrict__ row = xplane0 + rowoff;
            float v0 = row[xi0], v1 = row[xi1], v2 = row[xi2], v3 = row[xi3];
            float v4 = row[xi4], v5 = row[xi5], v6 = row[xi6];
            __stcs(orow0 +   0, v0);
            __stcs(orow0 +  32, v1);
            __stcs(orow0 +  64, v2);
            __stcs(orow0 +  96, v3);
            __stcs(orow0 + 128, v4);
            __stcs(orow0 + 160, v5);
            __stcs(orow0 + 192, v6);
        }
        // Plane 1: same indices, second plane (registers reused -> occupancy kept)
        {
            const float* __restrict__ row = xplane1 + rowoff;
            float v0 = row[xi0], v1 = row[xi1], v2 = row[xi2], v3 = row[xi3];
            float v4 = row[xi4], v5 = row[xi5], v6 = row[xi6];
            __stcs(orow1 +   0, v0);
            __stcs(orow1 +  32, v1);
            __stcs(orow1 +  64, v2);
            __stcs(orow1 +  96, v3);
            __stcs(orow1 + 128, v4);
            __stcs(orow1 + 160, v5);
            __stcs(orow1 + 192, v6);
        }
    }
}

extern "C" void kernel_launch(void* const* d_in, const int* in_sizes, int n_in,
                              void* d_out, int out_size)
{
    const float* x     = (const float*)d_in[0];
    const int*   sizes = (const int*)d_in[1];
    const int*   ox    = (const int*)d_in[2];
    const int*   oy    = (const int*)d_in[3];
    float*       out   = (float*)d_out;

    dim3 grid(NBANDS, NPAIRS);
    dim3 block(THREADS);
    make_cutouts_kernel<<<grid, block>>>(x, sizes, ox, oy, out);
}